// round 12
// baseline (speedup 1.0000x reference)
#include <cuda_runtime.h>
#include <math.h>

#define B_ 4
#define S_ 2048
#define D_ 2048
#define H_ 16
#define DH_ 128
#define QKV_N (3*D_)
#define BH_ (B_*H_)

// Planar scratch [b, h, s, dh] (allocation-free rule: device globals)
__device__ float g_q[(size_t)BH_*S_*DH_];      // 64 MiB  (part 0 of qkv)
__device__ float g_k[(size_t)BH_*S_*DH_];      // 64 MiB  (part 1 of qkv)
__device__ float g_v[(size_t)BH_*S_*DH_];      // 64 MiB  (part 2 of qkv)
__device__ float g_z[(size_t)B_*S_*D_];        // 64 MiB

// ---------------------------------------------------------------------------
// QKV GEMM with planar scatter epilogue.
// C[m, e] = sum_d A[m,d] * W[e,d];  each 128-col tile bn is one (part, head):
//   part = bn>>4, h = bn&15.  Row m = b*2048 + s.
// ---------------------------------------------------------------------------
__global__ __launch_bounds__(256, 2)
void qkv_gemm_planar(const float* __restrict__ A, const float* __restrict__ W)
{
    __shared__ float As[16*132];
    __shared__ float Bs[16*132];
    const int tid = threadIdx.x;
    const int bm = blockIdx.y, bn = blockIdx.x;
    const int tm = tid >> 4, tn = tid & 15;
    const int lrow = tid >> 2;          // 0..63
    const int lc4  = (tid & 3) * 4;     // 0,4,8,12
    const int K = D_;

    const float* Ag = A + (size_t)bm * 128 * K;
    const float* Bg = W + (size_t)bn * 128 * K;

    float acc[8][8];
#pragma unroll
    for (int i = 0; i < 8; ++i)
#pragma unroll
        for (int j = 0; j < 8; ++j) acc[i][j] = 0.f;

    for (int kt = 0; kt < K; kt += 16) {
#pragma unroll
        for (int i = 0; i < 2; ++i) {
            int row = lrow + i * 64;
            float4 va = *(const float4*)(Ag + (size_t)row * K + kt + lc4);
            float4 vb = *(const float4*)(Bg + (size_t)row * K + kt + lc4);
            As[(lc4+0)*132+row] = va.x; As[(lc4+1)*132+row] = va.y;
            As[(lc4+2)*132+row] = va.z; As[(lc4+3)*132+row] = va.w;
            Bs[(lc4+0)*132+row] = vb.x; Bs[(lc4+1)*132+row] = vb.y;
            Bs[(lc4+2)*132+row] = vb.z; Bs[(lc4+3)*132+row] = vb.w;
        }
        __syncthreads();
#pragma unroll
        for (int k = 0; k < 16; ++k) {
            float4 a0 = *(const float4*)&As[k*132 + tm*8];
            float4 a1 = *(const float4*)&As[k*132 + tm*8 + 4];
            float4 b0 = *(const float4*)&Bs[k*132 + tn*4];
            float4 b1 = *(const float4*)&Bs[k*132 + 64 + tn*4];
            float ra[8] = {a0.x,a0.y,a0.z,a0.w,a1.x,a1.y,a1.z,a1.w};
            float rb[8] = {b0.x,b0.y,b0.z,b0.w,b1.x,b1.y,b1.z,b1.w};
#pragma unroll
            for (int i2 = 0; i2 < 8; ++i2)
#pragma unroll
                for (int j = 0; j < 8; ++j)
                    acc[i2][j] = fmaf(ra[i2], rb[j], acc[i2][j]);
        }
        __syncthreads();
    }

    const int part = bn >> 4;
    const int hh   = bn & 15;
    float* dst = (part == 0) ? g_q : (part == 1) ? g_k : g_v;
#pragma unroll
    for (int i = 0; i < 8; ++i) {
        int m = bm*128 + tm*8 + i;
        int bb = m >> 11, ss = m & 2047;
        size_t rbase = ((size_t)(bb*16 + hh) * 2048 + ss) * 128;
        *(float4*)(dst + rbase + tn*4)      = make_float4(acc[i][0],acc[i][1],acc[i][2],acc[i][3]);
        *(float4*)(dst + rbase + 64 + tn*4) = make_float4(acc[i][4],acc[i][5],acc[i][6],acc[i][7]);
    }
}

// ---------------------------------------------------------------------------
// out GEMM: C[M,N] = A[M,K] * B[N,K]^T  (row-major, K-contiguous)
// ---------------------------------------------------------------------------
__global__ __launch_bounds__(256, 2)
void sgemm_tn(const float* __restrict__ A, const float* __restrict__ Bm,
              float* __restrict__ C, int M, int N, int K)
{
    __shared__ float As[16*132];
    __shared__ float Bs[16*132];
    const int tid = threadIdx.x;
    const int bm = blockIdx.y, bn = blockIdx.x;
    const int tm = tid >> 4, tn = tid & 15;
    const int lrow = tid >> 2;
    const int lc4  = (tid & 3) * 4;

    const float* Ag = A  + (size_t)bm * 128 * K;
    const float* Bg = Bm + (size_t)bn * 128 * K;

    float acc[8][8];
#pragma unroll
    for (int i = 0; i < 8; ++i)
#pragma unroll
        for (int j = 0; j < 8; ++j) acc[i][j] = 0.f;

    for (int kt = 0; kt < K; kt += 16) {
#pragma unroll
        for (int i = 0; i < 2; ++i) {
            int row = lrow + i * 64;
            float4 va = *(const float4*)(Ag + (size_t)row * K + kt + lc4);
            float4 vb = *(const float4*)(Bg + (size_t)row * K + kt + lc4);
            As[(lc4+0)*132+row] = va.x; As[(lc4+1)*132+row] = va.y;
            As[(lc4+2)*132+row] = va.z; As[(lc4+3)*132+row] = va.w;
            Bs[(lc4+0)*132+row] = vb.x; Bs[(lc4+1)*132+row] = vb.y;
            Bs[(lc4+2)*132+row] = vb.z; Bs[(lc4+3)*132+row] = vb.w;
        }
        __syncthreads();
#pragma unroll
        for (int k = 0; k < 16; ++k) {
            float4 a0 = *(const float4*)&As[k*132 + tm*8];
            float4 a1 = *(const float4*)&As[k*132 + tm*8 + 4];
            float4 b0 = *(const float4*)&Bs[k*132 + tn*4];
            float4 b1 = *(const float4*)&Bs[k*132 + 64 + tn*4];
            float ra[8] = {a0.x,a0.y,a0.z,a0.w,a1.x,a1.y,a1.z,a1.w};
            float rb[8] = {b0.x,b0.y,b0.z,b0.w,b1.x,b1.y,b1.z,b1.w};
#pragma unroll
            for (int i2 = 0; i2 < 8; ++i2)
#pragma unroll
                for (int j = 0; j < 8; ++j)
                    acc[i2][j] = fmaf(ra[i2], rb[j], acc[i2][j]);
        }
        __syncthreads();
    }
#pragma unroll
    for (int i = 0; i < 8; ++i) {
        size_t base = (size_t)(bm*128 + tm*8 + i) * N + bn*128;
        *(float4*)(C + base + tn*4)      = make_float4(acc[i][0],acc[i][1],acc[i][2],acc[i][3]);
        *(float4*)(C + base + 64 + tn*4) = make_float4(acc[i][4],acc[i][5],acc[i][6],acc[i][7]);
    }
}

// ---------------------------------------------------------------------------
// RoPE in place on planar g_q, g_k — half-split pairing, NEGATED angle PROBE:
//   out[i]    = x[i]*cos + x[i+64]*sin
//   out[i+64] = x[i+64]*cos - x[i]*sin
// ---------------------------------------------------------------------------
__global__ void rope_planar_kernel()
{
    int gid = blockIdx.x * blockDim.x + threadIdx.x;   // B*H*S*64 threads
    int i   = gid & 63;
    int row = gid >> 6;
    int s   = row & 2047;
    float inv = powf(10000.f, -(float)i / 64.f);
    float ang = (float)s * inv;
    float c, sn;
    sincosf(ang, &c, &sn);
    size_t p = (size_t)row * 128;
    {
        float x1 = g_q[p + i], x2 = g_q[p + i + 64];
        g_q[p + i]      = x1 * c + x2 * sn;
        g_q[p + i + 64] = x2 * c - x1 * sn;
    }
    {
        float x1 = g_k[p + i], x2 = g_k[p + i + 64];
        g_k[p + i]      = x1 * c + x2 * sn;
        g_k[p + i + 64] = x2 * c - x1 * sn;
    }
}

// ---------------------------------------------------------------------------
// Causal flash attention on planar q/k/v (standard orientation).
// Block = (64-row q-tile, one bh). 256 threads; thread t: row r = t>>2,
// quarter cq = t&3.
// ---------------------------------------------------------------------------
__global__ __launch_bounds__(256, 1)
void attn_kernel()
{
    extern __shared__ float sm[];
    float* Qs = sm;                  // 64 x 132 (128 used)
    float* Ks = Qs + 64*132;
    float* Vs = Ks + 64*132;
    float* Ss = Vs + 64*132;         // 64 x 65
    float* Ps = Ss + 64*65;          // 64 x 65

    const int tid = threadIdx.x;
    const int qt = blockIdx.x;
    const int bh = blockIdx.y;       // b*16 + h
    const int r  = tid >> 2;
    const int cq = tid & 3;
    const float scale = 0.08838834764831845f;   // 1/sqrt(128)

    const int row_g = qt*64 + r;
    const size_t plane = (size_t)bh * 2048;

    // Q: contiguous planar row, pre-scaled
    {
        const float* qrow = g_q + (plane + row_g) * 128;
#pragma unroll
        for (int jj = 0; jj < 8; ++jj) {
            int c = cq*32 + jj*4;
            float4 v = *(const float4*)(qrow + c);
            Qs[r*132 + c+0] = v.x * scale;
            Qs[r*132 + c+1] = v.y * scale;
            Qs[r*132 + c+2] = v.z * scale;
            Qs[r*132 + c+3] = v.w * scale;
        }
    }

    float m = -INFINITY, l = 0.f;
    float o[32];
#pragma unroll
    for (int j = 0; j < 32; ++j) o[j] = 0.f;

    for (int kt = 0; kt <= qt; ++kt) {
        __syncthreads();   // prev-iter Ps/Vs readers done; Qs writes done (iter 0)
        {
            int kr = kt*64 + r;
            const float* krow = g_k + (plane + kr) * 128;
            const float* vrow = g_v + (plane + kr) * 128;
#pragma unroll
            for (int jj = 0; jj < 8; ++jj) {
                int c = cq*32 + jj*4;
                *(float4*)&Ks[r*132 + c] = *(const float4*)(krow + c);
                *(float4*)&Vs[r*132 + c] = *(const float4*)(vrow + c);
            }
        }
        __syncthreads();

        // Scores for this thread's 16 columns
#pragma unroll 2
        for (int i = 0; i < 16; ++i) {
            int c = cq*16 + i;
            float s = 0.f;
#pragma unroll 8
            for (int d = 0; d < 128; d += 4) {
                float4 qv = *(const float4*)&Qs[r*132 + d];
                float4 kv = *(const float4*)&Ks[c*132 + d];
                s += qv.x*kv.x + qv.y*kv.y + qv.z*kv.z + qv.w*kv.w;
            }
            int col_g = kt*64 + c;
            Ss[r*65 + c] = (col_g > row_g) ? -INFINITY : s;
        }
        __syncthreads();

        // Row max (redundant across the row's 4 threads)
        float mx = -INFINITY;
#pragma unroll 8
        for (int c = 0; c < 64; ++c) mx = fmaxf(mx, Ss[r*65 + c]);
        float mn = fmaxf(m, mx);
        float f = expf(m - mn);           // first iter: exp(-inf)=0

#pragma unroll 2
        for (int i = 0; i < 16; ++i) {
            int c = cq*16 + i;
            Ps[r*65 + c] = expf(Ss[r*65 + c] - mn);   // masked -> 0
        }
        __syncthreads();

        float ps = 0.f;
#pragma unroll 8
        for (int c = 0; c < 64; ++c) ps += Ps[r*65 + c];
        l = l * f + ps;
        m = mn;
#pragma unroll
        for (int j = 0; j < 32; ++j) o[j] *= f;

        for (int c = 0; c < 64; ++c) {
            float p = Ps[r*65 + c];
            const float* vr = &Vs[c*132 + cq*32];
#pragma unroll
            for (int j = 0; j < 32; j += 4) {
                float4 vv = *(const float4*)(vr + j);
                o[j+0] = fmaf(p, vv.x, o[j+0]);
                o[j+1] = fmaf(p, vv.y, o[j+1]);
                o[j+2] = fmaf(p, vv.z, o[j+2]);
                o[j+3] = fmaf(p, vv.w, o[j+3]);
            }
        }
    }

    // Epilogue: z[b, row_g, h*128 + cq*32 + j] = o[j]/l
    float invl = 1.f / l;
    int b = bh >> 4, h = bh & 15;
    float* zp = g_z + (size_t)(b*S_ + row_g) * D_ + h * DH_ + cq*32;
#pragma unroll
    for (int j = 0; j < 32; j += 4) {
        *(float4*)(zp + j) = make_float4(o[j]*invl, o[j+1]*invl,
                                         o[j+2]*invl, o[j+3]*invl);
    }
}

// ---------------------------------------------------------------------------
extern "C" void kernel_launch(void* const* d_in, const int* in_sizes, int n_in,
                              void* d_out, int out_size)
{
    (void)out_size;
    const float* x    = nullptr;   // B*S*D   = 16,777,216
    const float* Wqkv = nullptr;   // 3*D*D   = 12,582,912
    const float* Wo   = nullptr;   // D*D     =  4,194,304
    for (int i = 0; i < n_in; ++i) {
        if      (in_sizes[i] == 16777216) x    = (const float*)d_in[i];
        else if (in_sizes[i] == 12582912) Wqkv = (const float*)d_in[i];
        else if (in_sizes[i] ==  4194304) Wo   = (const float*)d_in[i];
    }
    if (!x)    x    = (const float*)d_in[0];
    if (!Wqkv) Wqkv = (const float*)d_in[1];
    if (!Wo)   Wo   = (const float*)d_in[2];

    float* out = (float*)d_out;

    float* z = nullptr;
    cudaGetSymbolAddress((void**)&z, g_z);

    dim3 blk(256);

    // 1) planar q/k/v = x @ Wqkv^T  (scattered per-head)
    qkv_gemm_planar<<<dim3(QKV_N/128, (B_*S_)/128), blk>>>(x, Wqkv);

    // 2) RoPE in place on planar q,k — NEGATED-angle half-split (probe)
    rope_planar_kernel<<<(BH_*S_*64)/256, blk>>>();

    // 3) causal attention -> z
    const int smem = (64*132*3 + 64*65*2) * 4;   // 134,656 B
    cudaFuncSetAttribute(attn_kernel, cudaFuncAttributeMaxDynamicSharedMemorySize, smem);
    attn_kernel<<<dim3(S_/64, BH_), blk, smem>>>();

    // 4) out = z @ Wo^T
    sgemm_tn<<<dim3(D_/128, (B_*S_)/128), blk>>>(z, Wo, out, B_*S_, D_, D_);
}

// round 13
// speedup vs baseline: 3.1306x; 3.1306x over previous
#include <cuda_runtime.h>
#include <math.h>

#define B_ 4
#define S_ 2048
#define D_ 2048
#define H_ 16
#define DH_ 128
#define QKV_N (3*D_)
#define BH_ (B_*H_)

// Planar scratch [b, h, s, dh] (allocation-free rule: device globals)
__device__ float g_q[(size_t)BH_*S_*DH_];      // 64 MiB  (part 0 of qkv)
__device__ float g_k[(size_t)BH_*S_*DH_];      // 64 MiB  (part 1 of qkv)
__device__ float g_v[(size_t)BH_*S_*DH_];      // 64 MiB  (part 2 of qkv)
__device__ float g_z[(size_t)B_*S_*D_];        // 64 MiB

// ---------------------------------------------------------------------------
// QKV GEMM with planar scatter epilogue.
// C[m, e] = sum_d A[m,d] * W[e,d];  each 128-col tile bn is one (part, head):
//   part = bn>>4, h = bn&15.  Row m = b*2048 + s.
// ---------------------------------------------------------------------------
__global__ __launch_bounds__(256, 2)
void qkv_gemm_planar(const float* __restrict__ A, const float* __restrict__ W)
{
    __shared__ float As[16*132];
    __shared__ float Bs[16*132];
    const int tid = threadIdx.x;
    const int bm = blockIdx.y, bn = blockIdx.x;
    const int tm = tid >> 4, tn = tid & 15;
    const int lrow = tid >> 2;          // 0..63
    const int lc4  = (tid & 3) * 4;     // 0,4,8,12
    const int K = D_;

    const float* Ag = A + (size_t)bm * 128 * K;
    const float* Bg = W + (size_t)bn * 128 * K;

    float acc[8][8];
#pragma unroll
    for (int i = 0; i < 8; ++i)
#pragma unroll
        for (int j = 0; j < 8; ++j) acc[i][j] = 0.f;

    for (int kt = 0; kt < K; kt += 16) {
#pragma unroll
        for (int i = 0; i < 2; ++i) {
            int row = lrow + i * 64;
            float4 va = *(const float4*)(Ag + (size_t)row * K + kt + lc4);
            float4 vb = *(const float4*)(Bg + (size_t)row * K + kt + lc4);
            As[(lc4+0)*132+row] = va.x; As[(lc4+1)*132+row] = va.y;
            As[(lc4+2)*132+row] = va.z; As[(lc4+3)*132+row] = va.w;
            Bs[(lc4+0)*132+row] = vb.x; Bs[(lc4+1)*132+row] = vb.y;
            Bs[(lc4+2)*132+row] = vb.z; Bs[(lc4+3)*132+row] = vb.w;
        }
        __syncthreads();
#pragma unroll
        for (int k = 0; k < 16; ++k) {
            float4 a0 = *(const float4*)&As[k*132 + tm*8];
            float4 a1 = *(const float4*)&As[k*132 + tm*8 + 4];
            float4 b0 = *(const float4*)&Bs[k*132 + tn*4];
            float4 b1 = *(const float4*)&Bs[k*132 + 64 + tn*4];
            float ra[8] = {a0.x,a0.y,a0.z,a0.w,a1.x,a1.y,a1.z,a1.w};
            float rb[8] = {b0.x,b0.y,b0.z,b0.w,b1.x,b1.y,b1.z,b1.w};
#pragma unroll
            for (int i2 = 0; i2 < 8; ++i2)
#pragma unroll
                for (int j = 0; j < 8; ++j)
                    acc[i2][j] = fmaf(ra[i2], rb[j], acc[i2][j]);
        }
        __syncthreads();
    }

    const int part = bn >> 4;
    const int hh   = bn & 15;
    float* dst = (part == 0) ? g_q : (part == 1) ? g_k : g_v;
#pragma unroll
    for (int i = 0; i < 8; ++i) {
        int m = bm*128 + tm*8 + i;
        int bb = m >> 11, ss = m & 2047;
        size_t rbase = ((size_t)(bb*16 + hh) * 2048 + ss) * 128;
        *(float4*)(dst + rbase + tn*4)      = make_float4(acc[i][0],acc[i][1],acc[i][2],acc[i][3]);
        *(float4*)(dst + rbase + 64 + tn*4) = make_float4(acc[i][4],acc[i][5],acc[i][6],acc[i][7]);
    }
}

// ---------------------------------------------------------------------------
// out GEMM: C[M,N] = A[M,K] * B[N,K]^T  (row-major, K-contiguous)
// ---------------------------------------------------------------------------
__global__ __launch_bounds__(256, 2)
void sgemm_tn(const float* __restrict__ A, const float* __restrict__ Bm,
              float* __restrict__ C, int M, int N, int K)
{
    __shared__ float As[16*132];
    __shared__ float Bs[16*132];
    const int tid = threadIdx.x;
    const int bm = blockIdx.y, bn = blockIdx.x;
    const int tm = tid >> 4, tn = tid & 15;
    const int lrow = tid >> 2;
    const int lc4  = (tid & 3) * 4;

    const float* Ag = A  + (size_t)bm * 128 * K;
    const float* Bg = Bm + (size_t)bn * 128 * K;

    float acc[8][8];
#pragma unroll
    for (int i = 0; i < 8; ++i)
#pragma unroll
        for (int j = 0; j < 8; ++j) acc[i][j] = 0.f;

    for (int kt = 0; kt < K; kt += 16) {
#pragma unroll
        for (int i = 0; i < 2; ++i) {
            int row = lrow + i * 64;
            float4 va = *(const float4*)(Ag + (size_t)row * K + kt + lc4);
            float4 vb = *(const float4*)(Bg + (size_t)row * K + kt + lc4);
            As[(lc4+0)*132+row] = va.x; As[(lc4+1)*132+row] = va.y;
            As[(lc4+2)*132+row] = va.z; As[(lc4+3)*132+row] = va.w;
            Bs[(lc4+0)*132+row] = vb.x; Bs[(lc4+1)*132+row] = vb.y;
            Bs[(lc4+2)*132+row] = vb.z; Bs[(lc4+3)*132+row] = vb.w;
        }
        __syncthreads();
#pragma unroll
        for (int k = 0; k < 16; ++k) {
            float4 a0 = *(const float4*)&As[k*132 + tm*8];
            float4 a1 = *(const float4*)&As[k*132 + tm*8 + 4];
            float4 b0 = *(const float4*)&Bs[k*132 + tn*4];
            float4 b1 = *(const float4*)&Bs[k*132 + 64 + tn*4];
            float ra[8] = {a0.x,a0.y,a0.z,a0.w,a1.x,a1.y,a1.z,a1.w};
            float rb[8] = {b0.x,b0.y,b0.z,b0.w,b1.x,b1.y,b1.z,b1.w};
#pragma unroll
            for (int i2 = 0; i2 < 8; ++i2)
#pragma unroll
                for (int j = 0; j < 8; ++j)
                    acc[i2][j] = fmaf(ra[i2], rb[j], acc[i2][j]);
        }
        __syncthreads();
    }
#pragma unroll
    for (int i = 0; i < 8; ++i) {
        size_t base = (size_t)(bm*128 + tm*8 + i) * N + bn*128;
        *(float4*)(C + base + tn*4)      = make_float4(acc[i][0],acc[i][1],acc[i][2],acc[i][3]);
        *(float4*)(C + base + 64 + tn*4) = make_float4(acc[i][4],acc[i][5],acc[i][6],acc[i][7]);
    }
}

// ---------------------------------------------------------------------------
// RoPE in place on planar g_q, g_k — half-split pairing, negated angle
// (verified convention):
//   out[i]    = x[i]*cos + x[i+64]*sin
//   out[i+64] = x[i+64]*cos - x[i]*sin
// ---------------------------------------------------------------------------
__global__ void rope_planar_kernel()
{
    int gid = blockIdx.x * blockDim.x + threadIdx.x;   // B*H*S*64 threads
    int i   = gid & 63;
    int row = gid >> 6;
    int s   = row & 2047;
    float inv = powf(10000.f, -(float)i / 64.f);
    float ang = (float)s * inv;
    float c, sn;
    sincosf(ang, &c, &sn);
    size_t p = (size_t)row * 128;
    {
        float x1 = g_q[p + i], x2 = g_q[p + i + 64];
        g_q[p + i]      = x1 * c + x2 * sn;
        g_q[p + i + 64] = x2 * c - x1 * sn;
    }
    {
        float x1 = g_k[p + i], x2 = g_k[p + i + 64];
        g_k[p + i]      = x1 * c + x2 * sn;
        g_k[p + i + 64] = x2 * c - x1 * sn;
    }
}

// ---------------------------------------------------------------------------
// Causal flash attention, register-tiled. Block = (64-row q-tile, one bh).
// 256 threads as 16x16: thread (ty,tx) owns S rows ty*4..+3, S cols tx+16v,
// O dims tx*4..+3 and 64+tx*4..+3. Online softmax in registers (16-lane
// shuffle groups share constant ty).
// ---------------------------------------------------------------------------
__global__ __launch_bounds__(256, 1)
void attn_kernel()
{
    extern __shared__ float sm[];
    float* Qs = sm;                 // 64 x 128
    float* Ks = sm + 64*128;        // 64 x (stride 132)
    float* Vs = Ks + 64*132;        // 64 x 128
    float* Ps = Vs + 64*128;        // 64 x 64

    const int tid = threadIdx.x;
    const int qt = blockIdx.x;
    const int bh = blockIdx.y;      // b*16 + h
    const int ty = tid >> 4, tx = tid & 15;
    const float scale = 0.08838834764831845f;   // 1/sqrt(128)

    const size_t plane = (size_t)bh * 2048;

    // Load Q tile (planar contiguous rows), pre-scaled
#pragma unroll
    for (int it = 0; it < 8; ++it) {
        int idx = tid + it * 256;
        int r = idx >> 5, c4 = (idx & 31) * 4;
        float4 v = *(const float4*)(g_q + (plane + qt*64 + r) * 128 + c4);
        v.x *= scale; v.y *= scale; v.z *= scale; v.w *= scale;
        *(float4*)&Qs[r*128 + c4] = v;
    }

    float m[4], l[4], o[4][8];
#pragma unroll
    for (int u = 0; u < 4; ++u) {
        m[u] = -INFINITY; l[u] = 0.f;
#pragma unroll
        for (int j = 0; j < 8; ++j) o[u][j] = 0.f;
    }

    for (int kt = 0; kt <= qt; ++kt) {
        __syncthreads();   // protect Qs (first iter) / Ks,Vs,Ps readers (later)
#pragma unroll
        for (int it = 0; it < 8; ++it) {
            int idx = tid + it * 256;
            int r = idx >> 5, c4 = (idx & 31) * 4;
            *(float4*)&Ks[r*132 + c4] = *(const float4*)(g_k + (plane + kt*64 + r) * 128 + c4);
            *(float4*)&Vs[r*128 + c4] = *(const float4*)(g_v + (plane + kt*64 + r) * 128 + c4);
        }
        __syncthreads();

        // S = Q K^T (Q pre-scaled)
        float s4[4][4];
#pragma unroll
        for (int u = 0; u < 4; ++u)
#pragma unroll
            for (int v = 0; v < 4; ++v) s4[u][v] = 0.f;

#pragma unroll 4
        for (int d4 = 0; d4 < 32; ++d4) {
            float4 qv[4], kv[4];
#pragma unroll
            for (int u = 0; u < 4; ++u) qv[u] = *(const float4*)&Qs[(ty*4+u)*128 + d4*4];
#pragma unroll
            for (int v = 0; v < 4; ++v) kv[v] = *(const float4*)&Ks[(tx+16*v)*132 + d4*4];
#pragma unroll
            for (int u = 0; u < 4; ++u)
#pragma unroll
                for (int v = 0; v < 4; ++v) {
                    s4[u][v] = fmaf(qv[u].x, kv[v].x, s4[u][v]);
                    s4[u][v] = fmaf(qv[u].y, kv[v].y, s4[u][v]);
                    s4[u][v] = fmaf(qv[u].z, kv[v].z, s4[u][v]);
                    s4[u][v] = fmaf(qv[u].w, kv[v].w, s4[u][v]);
                }
        }

        if (kt == qt) {
#pragma unroll
            for (int u = 0; u < 4; ++u)
#pragma unroll
                for (int v = 0; v < 4; ++v)
                    if (tx + 16*v > ty*4 + u) s4[u][v] = -INFINITY;
        }

        // Online softmax: 16-lane groups share constant ty (XOR 1..8 stays in half)
#pragma unroll
        for (int u = 0; u < 4; ++u) {
            float mx = fmaxf(fmaxf(s4[u][0], s4[u][1]), fmaxf(s4[u][2], s4[u][3]));
#pragma unroll
            for (int off = 1; off < 16; off <<= 1)
                mx = fmaxf(mx, __shfl_xor_sync(0xffffffffu, mx, off));
            float mn = fmaxf(m[u], mx);
            float f = expf(m[u] - mn);   // first iter: exp(-inf)=0
            float pl = 0.f;
#pragma unroll
            for (int v = 0; v < 4; ++v) {
                float p = expf(s4[u][v] - mn);
                Ps[(ty*4+u)*64 + tx + 16*v] = p;
                pl += p;
            }
#pragma unroll
            for (int off = 1; off < 16; off <<= 1)
                pl += __shfl_xor_sync(0xffffffffu, pl, off);
            l[u] = l[u] * f + pl;
            m[u] = mn;
#pragma unroll
            for (int j = 0; j < 8; ++j) o[u][j] *= f;
        }
        __syncthreads();

        // O += P V
#pragma unroll 4
        for (int kv2 = 0; kv2 < 64; ++kv2) {
            float4 v0 = *(const float4*)&Vs[kv2*128 + tx*4];
            float4 v1 = *(const float4*)&Vs[kv2*128 + 64 + tx*4];
#pragma unroll
            for (int u = 0; u < 4; ++u) {
                float p = Ps[(ty*4+u)*64 + kv2];
                o[u][0] = fmaf(p, v0.x, o[u][0]);
                o[u][1] = fmaf(p, v0.y, o[u][1]);
                o[u][2] = fmaf(p, v0.z, o[u][2]);
                o[u][3] = fmaf(p, v0.w, o[u][3]);
                o[u][4] = fmaf(p, v1.x, o[u][4]);
                o[u][5] = fmaf(p, v1.y, o[u][5]);
                o[u][6] = fmaf(p, v1.z, o[u][6]);
                o[u][7] = fmaf(p, v1.w, o[u][7]);
            }
        }
    }

    // Epilogue: O/l -> z[b, s, h*128 + col]
    int b = bh >> 4, h = bh & 15;
#pragma unroll
    for (int u = 0; u < 4; ++u) {
        float inv = 1.f / l[u];
        size_t base = (size_t)(b*S_ + qt*64 + ty*4 + u) * D_ + h * DH_;
        *(float4*)(g_z + base + tx*4) =
            make_float4(o[u][0]*inv, o[u][1]*inv, o[u][2]*inv, o[u][3]*inv);
        *(float4*)(g_z + base + 64 + tx*4) =
            make_float4(o[u][4]*inv, o[u][5]*inv, o[u][6]*inv, o[u][7]*inv);
    }
}

// ---------------------------------------------------------------------------
extern "C" void kernel_launch(void* const* d_in, const int* in_sizes, int n_in,
                              void* d_out, int out_size)
{
    (void)out_size;
    const float* x    = nullptr;   // B*S*D   = 16,777,216
    const float* Wqkv = nullptr;   // 3*D*D   = 12,582,912
    const float* Wo   = nullptr;   // D*D     =  4,194,304
    for (int i = 0; i < n_in; ++i) {
        if      (in_sizes[i] == 16777216) x    = (const float*)d_in[i];
        else if (in_sizes[i] == 12582912) Wqkv = (const float*)d_in[i];
        else if (in_sizes[i] ==  4194304) Wo   = (const float*)d_in[i];
    }
    if (!x)    x    = (const float*)d_in[0];
    if (!Wqkv) Wqkv = (const float*)d_in[1];
    if (!Wo)   Wo   = (const float*)d_in[2];

    float* out = (float*)d_out;

    float* z = nullptr;
    cudaGetSymbolAddress((void**)&z, g_z);

    dim3 blk(256);

    // 1) planar q/k/v = x @ Wqkv^T  (scattered per-head)
    qkv_gemm_planar<<<dim3(QKV_N/128, (B_*S_)/128), blk>>>(x, Wqkv);

    // 2) RoPE in place on planar q,k (negated-angle half-split)
    rope_planar_kernel<<<(BH_*S_*64)/256, blk>>>();

    // 3) causal attention -> z  (register-tiled)
    const int smem = (64*128 + 64*132 + 64*128 + 64*64) * 4;   // 115,712 B
    cudaFuncSetAttribute(attn_kernel, cudaFuncAttributeMaxDynamicSharedMemorySize, smem);
    attn_kernel<<<dim3(S_/64, BH_), blk, smem>>>();

    // 4) out = z @ Wo^T
    sgemm_tn<<<dim3(D_/128, (B_*S_)/128), blk>>>(z, Wo, out, B_*S_, D_, D_);
}

// round 15
// speedup vs baseline: 4.8898x; 1.5619x over previous
#include <cuda_runtime.h>
#include <cuda_bf16.h>
#include <cstdint>
#include <math.h>

#define B_ 4
#define S_ 2048
#define D_ 2048
#define H_ 16
#define DH_ 128
#define QKV_N (3*D_)
#define BH_ (B_*H_)

// Planar scratch [b, h, s, dh] (allocation-free rule: device globals)
__device__ float g_q[(size_t)BH_*S_*DH_];      // 64 MiB
__device__ float g_k[(size_t)BH_*S_*DH_];      // 64 MiB
__device__ float g_v[(size_t)BH_*S_*DH_];      // 64 MiB
__device__ float g_z[(size_t)B_*S_*D_];        // 64 MiB

__device__ __forceinline__ unsigned smem_u32(const void* p) {
    return (unsigned)__cvta_generic_to_shared(p);
}

#define LDSM4(r0,r1,r2,r3,addr) asm volatile( \
    "ldmatrix.sync.aligned.m8n8.x4.shared.b16 {%0,%1,%2,%3}, [%4];" \
    : "=r"(r0),"=r"(r1),"=r"(r2),"=r"(r3) : "r"(addr))

#define MMA16816(d,a,b0,b1) asm volatile( \
    "mma.sync.aligned.m16n8k16.row.col.f32.bf16.bf16.f32 " \
    "{%0,%1,%2,%3},{%4,%5,%6,%7},{%8,%9},{%0,%1,%2,%3};" \
    : "+f"((d)[0]),"+f"((d)[1]),"+f"((d)[2]),"+f"((d)[3]) \
    : "r"((a)[0]),"r"((a)[1]),"r"((a)[2]),"r"((a)[3]),"r"(b0),"r"(b1))

// ---------------------------------------------------------------------------
// bf16x3 GEMM: C[M,N] = A[M,K] * W[N,K]^T with fp32-grade accuracy.
// Each fp32 input is split a = hi + lo (bf16 each); C += Ah*Bh + Ah*Bl + Al*Bh.
// Block 128x128x32, 8 warps (4x2), warp tile 32x64 via m16n8k16 fragments.
// smem stride 40 bf16 (80B): conflict-free for b32 and all ldmatrix phases.
// mode 0: store C (ldN = N). mode 1: scatter to planar g_q/g_k/g_v.
// ---------------------------------------------------------------------------
__global__ __launch_bounds__(256)
void gemm_bf16x3(const float* __restrict__ A, const float* __restrict__ W,
                 float* __restrict__ C, int N, int K, int mode)
{
    __shared__ __nv_bfloat16 Ah[128*40], Al[128*40], Bh[128*40], Bl[128*40];

    const int tid  = threadIdx.x;
    const int bm   = blockIdx.y, bn = blockIdx.x;
    const int lane = tid & 31,  wid = tid >> 5;
    const int wm   = wid & 3,   wn  = wid >> 2;    // warp grid 4 x 2

    float acc[2][8][4];
#pragma unroll
    for (int mi = 0; mi < 2; ++mi)
#pragma unroll
        for (int n8 = 0; n8 < 8; ++n8)
#pragma unroll
            for (int t = 0; t < 4; ++t) acc[mi][n8][t] = 0.f;

    const float* Ag = A + (size_t)bm * 128 * K;
    const float* Bg = W + (size_t)bn * 128 * K;

    const int rsel = lane & 15;
    const int ksel = (lane >> 4) * 8;

    for (int kt = 0; kt < K; kt += 32) {
        __syncthreads();
#pragma unroll
        for (int it = 0; it < 4; ++it) {
            int idx = tid + it * 256;
            int row = idx >> 3, c4 = (idx & 7) * 4;
            float4 va = *(const float4*)(Ag + (size_t)row * K + kt + c4);
            float4 vb = *(const float4*)(Bg + (size_t)row * K + kt + c4);

            __nv_bfloat162 h01, h23, l01, l23;
            h01.x = __float2bfloat16(va.x);
            h01.y = __float2bfloat16(va.y);
            h23.x = __float2bfloat16(va.z);
            h23.y = __float2bfloat16(va.w);
            l01.x = __float2bfloat16(va.x - __bfloat162float(h01.x));
            l01.y = __float2bfloat16(va.y - __bfloat162float(h01.y));
            l23.x = __float2bfloat16(va.z - __bfloat162float(h23.x));
            l23.y = __float2bfloat16(va.w - __bfloat162float(h23.y));
            *(__nv_bfloat162*)&Ah[row*40 + c4]     = h01;
            *(__nv_bfloat162*)&Ah[row*40 + c4 + 2] = h23;
            *(__nv_bfloat162*)&Al[row*40 + c4]     = l01;
            *(__nv_bfloat162*)&Al[row*40 + c4 + 2] = l23;

            h01.x = __float2bfloat16(vb.x);
            h01.y = __float2bfloat16(vb.y);
            h23.x = __float2bfloat16(vb.z);
            h23.y = __float2bfloat16(vb.w);
            l01.x = __float2bfloat16(vb.x - __bfloat162float(h01.x));
            l01.y = __float2bfloat16(vb.y - __bfloat162float(h01.y));
            l23.x = __float2bfloat16(vb.z - __bfloat162float(h23.x));
            l23.y = __float2bfloat16(vb.w - __bfloat162float(h23.y));
            *(__nv_bfloat162*)&Bh[row*40 + c4]     = h01;
            *(__nv_bfloat162*)&Bh[row*40 + c4 + 2] = h23;
            *(__nv_bfloat162*)&Bl[row*40 + c4]     = l01;
            *(__nv_bfloat162*)&Bl[row*40 + c4 + 2] = l23;
        }
        __syncthreads();

#pragma unroll
        for (int kk = 0; kk < 32; kk += 16) {
            unsigned ah[2][4], al[2][4], bh[4][4], bl[4][4];
#pragma unroll
            for (int mi = 0; mi < 2; ++mi) {
                int off = (wm*32 + mi*16 + rsel)*40 + kk + ksel;
                LDSM4(ah[mi][0],ah[mi][1],ah[mi][2],ah[mi][3], smem_u32(&Ah[off]));
                LDSM4(al[mi][0],al[mi][1],al[mi][2],al[mi][3], smem_u32(&Al[off]));
            }
#pragma unroll
            for (int nj = 0; nj < 4; ++nj) {
                int off = (wn*64 + nj*16 + rsel)*40 + kk + ksel;
                LDSM4(bh[nj][0],bh[nj][1],bh[nj][2],bh[nj][3], smem_u32(&Bh[off]));
                LDSM4(bl[nj][0],bl[nj][1],bl[nj][2],bl[nj][3], smem_u32(&Bl[off]));
            }
#pragma unroll
            for (int mi = 0; mi < 2; ++mi)
#pragma unroll
                for (int nj = 0; nj < 4; ++nj)
#pragma unroll
                    for (int t = 0; t < 2; ++t) {
                        float* d = acc[mi][nj*2 + t];
                        MMA16816(d, ah[mi], bh[nj][t], bh[nj][2+t]);   // hi*hi
                        MMA16816(d, ah[mi], bl[nj][t], bl[nj][2+t]);   // hi*lo
                        MMA16816(d, al[mi], bh[nj][t], bh[nj][2+t]);   // lo*hi
                    }
        }
    }

    // Epilogue. C-frag: rows lane/4 (+8), cols 2*(lane%4)+{0,1} per n8 tile.
    const int r_in = lane >> 2;
    const int c_in = (lane & 3) * 2;
    if (mode == 0) {
#pragma unroll
        for (int mi = 0; mi < 2; ++mi) {
            int m0 = bm*128 + wm*32 + mi*16 + r_in;
#pragma unroll
            for (int n8 = 0; n8 < 8; ++n8) {
                int col = bn*128 + wn*64 + n8*8 + c_in;
                *(float2*)&C[(size_t)m0*N + col] =
                    make_float2(acc[mi][n8][0], acc[mi][n8][1]);
                *(float2*)&C[(size_t)(m0+8)*N + col] =
                    make_float2(acc[mi][n8][2], acc[mi][n8][3]);
            }
        }
    } else {
        const int part = bn >> 4, hh = bn & 15;
        float* dst = (part == 0) ? g_q : (part == 1) ? g_k : g_v;
#pragma unroll
        for (int mi = 0; mi < 2; ++mi) {
            int m0 = bm*128 + wm*32 + mi*16 + r_in;    // tile fits one batch (2048%128==0)
            int bb = m0 >> 11, ss = m0 & 2047;
            size_t r0 = ((size_t)(bb*16 + hh) * 2048 + ss) * 128;
            size_t r1 = r0 + 8 * 128;
#pragma unroll
            for (int n8 = 0; n8 < 8; ++n8) {
                int col = wn*64 + n8*8 + c_in;
                *(float2*)&dst[r0 + col] = make_float2(acc[mi][n8][0], acc[mi][n8][1]);
                *(float2*)&dst[r1 + col] = make_float2(acc[mi][n8][2], acc[mi][n8][3]);
            }
        }
    }
}

// ---------------------------------------------------------------------------
// RoPE in place on planar g_q, g_k — half-split pairing, negated angle
// (verified convention):
//   out[i]    = x[i]*cos + x[i+64]*sin
//   out[i+64] = x[i+64]*cos - x[i]*sin
// ---------------------------------------------------------------------------
__global__ void rope_planar_kernel()
{
    int gid = blockIdx.x * blockDim.x + threadIdx.x;   // B*H*S*64 threads
    int i   = gid & 63;
    int row = gid >> 6;
    int s   = row & 2047;
    float inv = powf(10000.f, -(float)i / 64.f);
    float ang = (float)s * inv;
    float c, sn;
    sincosf(ang, &c, &sn);
    size_t p = (size_t)row * 128;
    {
        float x1 = g_q[p + i], x2 = g_q[p + i + 64];
        g_q[p + i]      = x1 * c + x2 * sn;
        g_q[p + i + 64] = x2 * c - x1 * sn;
    }
    {
        float x1 = g_k[p + i], x2 = g_k[p + i + 64];
        g_k[p + i]      = x1 * c + x2 * sn;
        g_k[p + i + 64] = x2 * c - x1 * sn;
    }
}

// ---------------------------------------------------------------------------
// Causal flash attention, register-tiled (verified). Block = (64-row q-tile,
// one bh). 256 threads as 16x16.
// ---------------------------------------------------------------------------
__global__ __launch_bounds__(256, 1)
void attn_kernel()
{
    extern __shared__ float sm[];
    float* Qs = sm;                 // 64 x 128
    float* Ks = sm + 64*128;        // 64 x (stride 132)
    float* Vs = Ks + 64*132;        // 64 x 128
    float* Ps = Vs + 64*128;        // 64 x 64

    const int tid = threadIdx.x;
    const int qt = blockIdx.x;
    const int bh = blockIdx.y;      // b*16 + h
    const int ty = tid >> 4, tx = tid & 15;
    const float scale = 0.08838834764831845f;   // 1/sqrt(128)

    const size_t plane = (size_t)bh * 2048;

#pragma unroll
    for (int it = 0; it < 8; ++it) {
        int idx = tid + it * 256;
        int r = idx >> 5, c4 = (idx & 31) * 4;
        float4 v = *(const float4*)(g_q + (plane + qt*64 + r) * 128 + c4);
        v.x *= scale; v.y *= scale; v.z *= scale; v.w *= scale;
        *(float4*)&Qs[r*128 + c4] = v;
    }

    float m[4], l[4], o[4][8];
#pragma unroll
    for (int u = 0; u < 4; ++u) {
        m[u] = -INFINITY; l[u] = 0.f;
#pragma unroll
        for (int j = 0; j < 8; ++j) o[u][j] = 0.f;
    }

    for (int kt = 0; kt <= qt; ++kt) {
        __syncthreads();
#pragma unroll
        for (int it = 0; it < 8; ++it) {
            int idx = tid + it * 256;
            int r = idx >> 5, c4 = (idx & 31) * 4;
            *(float4*)&Ks[r*132 + c4] = *(const float4*)(g_k + (plane + kt*64 + r) * 128 + c4);
            *(float4*)&Vs[r*128 + c4] = *(const float4*)(g_v + (plane + kt*64 + r) * 128 + c4);
        }
        __syncthreads();

        float s4[4][4];
#pragma unroll
        for (int u = 0; u < 4; ++u)
#pragma unroll
            for (int v = 0; v < 4; ++v) s4[u][v] = 0.f;

#pragma unroll 4
        for (int d4 = 0; d4 < 32; ++d4) {
            float4 qv[4], kv[4];
#pragma unroll
            for (int u = 0; u < 4; ++u) qv[u] = *(const float4*)&Qs[(ty*4+u)*128 + d4*4];
#pragma unroll
            for (int v = 0; v < 4; ++v) kv[v] = *(const float4*)&Ks[(tx+16*v)*132 + d4*4];
#pragma unroll
            for (int u = 0; u < 4; ++u)
#pragma unroll
                for (int v = 0; v < 4; ++v) {
                    s4[u][v] = fmaf(qv[u].x, kv[v].x, s4[u][v]);
                    s4[u][v] = fmaf(qv[u].y, kv[v].y, s4[u][v]);
                    s4[u][v] = fmaf(qv[u].z, kv[v].z, s4[u][v]);
                    s4[u][v] = fmaf(qv[u].w, kv[v].w, s4[u][v]);
                }
        }

        if (kt == qt) {
#pragma unroll
            for (int u = 0; u < 4; ++u)
#pragma unroll
                for (int v = 0; v < 4; ++v)
                    if (tx + 16*v > ty*4 + u) s4[u][v] = -INFINITY;
        }

#pragma unroll
        for (int u = 0; u < 4; ++u) {
            float mx = fmaxf(fmaxf(s4[u][0], s4[u][1]), fmaxf(s4[u][2], s4[u][3]));
#pragma unroll
            for (int off = 1; off < 16; off <<= 1)
                mx = fmaxf(mx, __shfl_xor_sync(0xffffffffu, mx, off));
            float mn = fmaxf(m[u], mx);
            float f = expf(m[u] - mn);
            float pl = 0.f;
#pragma unroll
            for (int v = 0; v < 4; ++v) {
                float p = expf(s4[u][v] - mn);
                Ps[(ty*4+u)*64 + tx + 16*v] = p;
                pl += p;
            }
#pragma unroll
            for (int off = 1; off < 16; off <<= 1)
                pl += __shfl_xor_sync(0xffffffffu, pl, off);
            l[u] = l[u] * f + pl;
            m[u] = mn;
#pragma unroll
            for (int j = 0; j < 8; ++j) o[u][j] *= f;
        }
        __syncthreads();

#pragma unroll 4
        for (int kv2 = 0; kv2 < 64; ++kv2) {
            float4 v0 = *(const float4*)&Vs[kv2*128 + tx*4];
            float4 v1 = *(const float4*)&Vs[kv2*128 + 64 + tx*4];
#pragma unroll
            for (int u = 0; u < 4; ++u) {
                float p = Ps[(ty*4+u)*64 + kv2];
                o[u][0] = fmaf(p, v0.x, o[u][0]);
                o[u][1] = fmaf(p, v0.y, o[u][1]);
                o[u][2] = fmaf(p, v0.z, o[u][2]);
                o[u][3] = fmaf(p, v0.w, o[u][3]);
                o[u][4] = fmaf(p, v1.x, o[u][4]);
                o[u][5] = fmaf(p, v1.y, o[u][5]);
                o[u][6] = fmaf(p, v1.z, o[u][6]);
                o[u][7] = fmaf(p, v1.w, o[u][7]);
            }
        }
    }

    int b = bh >> 4, h = bh & 15;
#pragma unroll
    for (int u = 0; u < 4; ++u) {
        float inv = 1.f / l[u];
        size_t base = (size_t)(b*S_ + qt*64 + ty*4 + u) * D_ + h * DH_;
        *(float4*)(g_z + base + tx*4) =
            make_float4(o[u][0]*inv, o[u][1]*inv, o[u][2]*inv, o[u][3]*inv);
        *(float4*)(g_z + base + 64 + tx*4) =
            make_float4(o[u][4]*inv, o[u][5]*inv, o[u][6]*inv, o[u][7]*inv);
    }
}

// ---------------------------------------------------------------------------
extern "C" void kernel_launch(void* const* d_in, const int* in_sizes, int n_in,
                              void* d_out, int out_size)
{
    (void)out_size;
    const float* x    = nullptr;   // B*S*D   = 16,777,216
    const float* Wqkv = nullptr;   // 3*D*D   = 12,582,912
    const float* Wo   = nullptr;   // D*D     =  4,194,304
    for (int i = 0; i < n_in; ++i) {
        if      (in_sizes[i] == 16777216) x    = (const float*)d_in[i];
        else if (in_sizes[i] == 12582912) Wqkv = (const float*)d_in[i];
        else if (in_sizes[i] ==  4194304) Wo   = (const float*)d_in[i];
    }
    if (!x)    x    = (const float*)d_in[0];
    if (!Wqkv) Wqkv = (const float*)d_in[1];
    if (!Wo)   Wo   = (const float*)d_in[2];

    float* out = (float*)d_out;

    float* z = nullptr;
    cudaGetSymbolAddress((void**)&z, g_z);

    dim3 blk(256);

    // 1) planar q/k/v = x @ Wqkv^T   (bf16x3 tensor-core, scatter epilogue)
    gemm_bf16x3<<<dim3(QKV_N/128, (B_*S_)/128), blk>>>(x, Wqkv, nullptr, QKV_N, D_, 1);

    // 2) RoPE in place on planar q,k (negated-angle half-split)
    rope_planar_kernel<<<(BH_*S_*64)/256, blk>>>();

    // 3) causal attention -> z  (register-tiled fp32)
    const int smem = (64*128 + 64*132 + 64*128 + 64*64) * 4;   // 115,712 B
    cudaFuncSetAttribute(attn_kernel, cudaFuncAttributeMaxDynamicSharedMemorySize, smem);
    attn_kernel<<<dim3(S_/64, BH_), blk, smem>>>();

    // 4) out = z @ Wo^T   (bf16x3 tensor-core)
    gemm_bf16x3<<<dim3(D_/128, (B_*S_)/128), blk>>>(z, Wo, out, D_, D_, 0);
}

// round 16
// speedup vs baseline: 5.1941x; 1.0622x over previous
#include <cuda_runtime.h>
#include <cuda_bf16.h>
#include <cstdint>
#include <math.h>

#define B_ 4
#define S_ 2048
#define D_ 2048
#define H_ 16
#define DH_ 128
#define QKV_N (3*D_)
#define BH_ (B_*H_)

// Planar fp32 scratch (allocation-free rule: device globals)
__device__ float g_q[(size_t)BH_*S_*DH_];      // 64 MiB
__device__ float g_k[(size_t)BH_*S_*DH_];      // 64 MiB
__device__ float g_v[(size_t)BH_*S_*DH_];      // 64 MiB
__device__ float g_z[(size_t)B_*S_*D_];        // 64 MiB

// Pre-split bf16 hi/lo operands
__device__ __nv_bfloat16 g_xh[(size_t)B_*S_*D_],  g_xl[(size_t)B_*S_*D_];    // 32 MiB ea
__device__ __nv_bfloat16 g_wh[(size_t)QKV_N*D_],  g_wl[(size_t)QKV_N*D_];    // 24 MiB ea
__device__ __nv_bfloat16 g_woh[(size_t)D_*D_],    g_wol[(size_t)D_*D_];      //  8 MiB ea
__device__ __nv_bfloat16 g_zh[(size_t)B_*S_*D_],  g_zl[(size_t)B_*S_*D_];    // 32 MiB ea

__device__ __forceinline__ unsigned smem_u32(const void* p) {
    return (unsigned)__cvta_generic_to_shared(p);
}

#define LDSM4(r0,r1,r2,r3,addr) asm volatile( \
    "ldmatrix.sync.aligned.m8n8.x4.shared.b16 {%0,%1,%2,%3}, [%4];" \
    : "=r"(r0),"=r"(r1),"=r"(r2),"=r"(r3) : "r"(addr))

#define MMA16816(d,a,b0,b1) asm volatile( \
    "mma.sync.aligned.m16n8k16.row.col.f32.bf16.bf16.f32 " \
    "{%0,%1,%2,%3},{%4,%5,%6,%7},{%8,%9},{%0,%1,%2,%3};" \
    : "+f"((d)[0]),"+f"((d)[1]),"+f"((d)[2]),"+f"((d)[3]) \
    : "r"((a)[0]),"r"((a)[1]),"r"((a)[2]),"r"((a)[3]),"r"(b0),"r"(b1))

#define CP_ASYNC16(dst_u32, src_ptr) asm volatile( \
    "cp.async.ca.shared.global [%0], [%1], 16;" :: "r"(dst_u32), "l"(src_ptr))

// ---------------------------------------------------------------------------
// split: fp32 -> (hi, lo) bf16.  4 elems/thread, vectorized.
// ---------------------------------------------------------------------------
__global__ void split_kernel(const float* __restrict__ src,
                             __nv_bfloat16* __restrict__ hi,
                             __nv_bfloat16* __restrict__ lo)
{
    size_t i = ((size_t)blockIdx.x * blockDim.x + threadIdx.x) * 4;
    float4 v = *(const float4*)(src + i);
    __nv_bfloat162 h01, h23, l01, l23;
    h01.x = __float2bfloat16(v.x);  h01.y = __float2bfloat16(v.y);
    h23.x = __float2bfloat16(v.z);  h23.y = __float2bfloat16(v.w);
    l01.x = __float2bfloat16(v.x - __bfloat162float(h01.x));
    l01.y = __float2bfloat16(v.y - __bfloat162float(h01.y));
    l23.x = __float2bfloat16(v.z - __bfloat162float(h23.x));
    l23.y = __float2bfloat16(v.w - __bfloat162float(h23.y));
    *(__nv_bfloat162*)(hi + i)     = h01;
    *(__nv_bfloat162*)(hi + i + 2) = h23;
    *(__nv_bfloat162*)(lo + i)     = l01;
    *(__nv_bfloat162*)(lo + i + 2) = l23;
}

// ---------------------------------------------------------------------------
// bf16x3 GEMM on PRE-SPLIT inputs, cp.async double-buffered.
// C[M,N] = A[M,K]*W[N,K]^T via Ah*Bh + Ah*Bl + Al*Bh.
// Block 128x128x32, 8 warps (4x2), warp tile 32x64 (m16n8k16).
// smem: 2 stages x 4 arrays x 128 x 40 bf16 (stride 40 = conflict-free).
// mode 0: C[m*N+col].  mode 1: scatter to planar g_q/g_k/g_v.
// ---------------------------------------------------------------------------
__global__ __launch_bounds__(256)
void gemm3(const __nv_bfloat16* __restrict__ Ahg, const __nv_bfloat16* __restrict__ Alg,
           const __nv_bfloat16* __restrict__ Bhg, const __nv_bfloat16* __restrict__ Blg,
           float* __restrict__ C, int N, int K, int mode)
{
    extern __shared__ __nv_bfloat16 smem[];   // [2][4][128*40]

    const int tid  = threadIdx.x;
    const int bm   = blockIdx.y, bn = blockIdx.x;
    const int lane = tid & 31,  wid = tid >> 5;
    const int wm   = wid & 3,   wn  = wid >> 2;    // warp grid 4 x 2

    float acc[2][8][4];
#pragma unroll
    for (int mi = 0; mi < 2; ++mi)
#pragma unroll
        for (int n8 = 0; n8 < 8; ++n8)
#pragma unroll
            for (int t = 0; t < 4; ++t) acc[mi][n8][t] = 0.f;

    const __nv_bfloat16* gsrc[4] = {
        Ahg + (size_t)bm * 128 * K, Alg + (size_t)bm * 128 * K,
        Bhg + (size_t)bn * 128 * K, Blg + (size_t)bn * 128 * K };

    const int lrow = tid >> 2;            // 0..63 (x2 iters -> 128 rows)
    const int lch  = (tid & 3) * 8;       // 0,8,16,24 (16B chunks)

    auto load_stage = [&](int st, int kt) {
#pragma unroll
        for (int arr = 0; arr < 4; ++arr) {
            const __nv_bfloat16* g = gsrc[arr];
            __nv_bfloat16* s = smem + (size_t)(st*4 + arr) * (128*40);
#pragma unroll
            for (int it = 0; it < 2; ++it) {
                int row = lrow + it * 64;
                CP_ASYNC16(smem_u32(s + row*40 + lch),
                           g + (size_t)row * K + kt + lch);
            }
        }
        asm volatile("cp.async.commit_group;" ::);
    };

    const int rsel = lane & 15;
    const int ksel = (lane >> 4) * 8;
    const int T = K / 32;

    load_stage(0, 0);

    for (int t = 0; t < T; ++t) {
        if (t + 1 < T) {
            load_stage((t + 1) & 1, (t + 1) * 32);
            asm volatile("cp.async.wait_group 1;" ::);
        } else {
            asm volatile("cp.async.wait_group 0;" ::);
        }
        __syncthreads();

        const int st = t & 1;
        const __nv_bfloat16* Ahs = smem + (size_t)(st*4 + 0) * (128*40);
        const __nv_bfloat16* Als = smem + (size_t)(st*4 + 1) * (128*40);
        const __nv_bfloat16* Bhs = smem + (size_t)(st*4 + 2) * (128*40);
        const __nv_bfloat16* Bls = smem + (size_t)(st*4 + 3) * (128*40);

#pragma unroll
        for (int kk = 0; kk < 32; kk += 16) {
            unsigned ah[2][4], al[2][4], bh[4][4], bl[4][4];
#pragma unroll
            for (int mi = 0; mi < 2; ++mi) {
                int off = (wm*32 + mi*16 + rsel)*40 + kk + ksel;
                LDSM4(ah[mi][0],ah[mi][1],ah[mi][2],ah[mi][3], smem_u32(Ahs + off));
                LDSM4(al[mi][0],al[mi][1],al[mi][2],al[mi][3], smem_u32(Als + off));
            }
#pragma unroll
            for (int nj = 0; nj < 4; ++nj) {
                int off = (wn*64 + nj*16 + rsel)*40 + kk + ksel;
                LDSM4(bh[nj][0],bh[nj][1],bh[nj][2],bh[nj][3], smem_u32(Bhs + off));
                LDSM4(bl[nj][0],bl[nj][1],bl[nj][2],bl[nj][3], smem_u32(Bls + off));
            }
#pragma unroll
            for (int mi = 0; mi < 2; ++mi)
#pragma unroll
                for (int nj = 0; nj < 4; ++nj)
#pragma unroll
                    for (int t2 = 0; t2 < 2; ++t2) {
                        float* d = acc[mi][nj*2 + t2];
                        MMA16816(d, ah[mi], bh[nj][t2], bh[nj][2+t2]);   // hi*hi
                        MMA16816(d, ah[mi], bl[nj][t2], bl[nj][2+t2]);   // hi*lo
                        MMA16816(d, al[mi], bh[nj][t2], bh[nj][2+t2]);   // lo*hi
                    }
        }
        __syncthreads();
    }

    // Epilogue. C-frag: rows lane/4 (+8), cols 2*(lane%4)+{0,1} per n8 tile.
    const int r_in = lane >> 2;
    const int c_in = (lane & 3) * 2;
    if (mode == 0) {
#pragma unroll
        for (int mi = 0; mi < 2; ++mi) {
            int m0 = bm*128 + wm*32 + mi*16 + r_in;
#pragma unroll
            for (int n8 = 0; n8 < 8; ++n8) {
                int col = bn*128 + wn*64 + n8*8 + c_in;
                *(float2*)&C[(size_t)m0*N + col] =
                    make_float2(acc[mi][n8][0], acc[mi][n8][1]);
                *(float2*)&C[(size_t)(m0+8)*N + col] =
                    make_float2(acc[mi][n8][2], acc[mi][n8][3]);
            }
        }
    } else {
        const int part = bn >> 4, hh = bn & 15;
        float* dst = (part == 0) ? g_q : (part == 1) ? g_k : g_v;
#pragma unroll
        for (int mi = 0; mi < 2; ++mi) {
            int m0 = bm*128 + wm*32 + mi*16 + r_in;    // tile fits one batch
            int bb = m0 >> 11, ss = m0 & 2047;
            size_t r0 = ((size_t)(bb*16 + hh) * 2048 + ss) * 128;
            size_t r1 = r0 + 8 * 128;
#pragma unroll
            for (int n8 = 0; n8 < 8; ++n8) {
                int col = wn*64 + n8*8 + c_in;
                *(float2*)&dst[r0 + col] = make_float2(acc[mi][n8][0], acc[mi][n8][1]);
                *(float2*)&dst[r1 + col] = make_float2(acc[mi][n8][2], acc[mi][n8][3]);
            }
        }
    }
}

// ---------------------------------------------------------------------------
// RoPE in place on planar g_q, g_k — half-split pairing, negated angle
// (verified convention).
// ---------------------------------------------------------------------------
__global__ void rope_planar_kernel()
{
    int gid = blockIdx.x * blockDim.x + threadIdx.x;   // B*H*S*64 threads
    int i   = gid & 63;
    int row = gid >> 6;
    int s   = row & 2047;
    float inv = powf(10000.f, -(float)i / 64.f);
    float ang = (float)s * inv;
    float c, sn;
    sincosf(ang, &c, &sn);
    size_t p = (size_t)row * 128;
    {
        float x1 = g_q[p + i], x2 = g_q[p + i + 64];
        g_q[p + i]      = x1 * c + x2 * sn;
        g_q[p + i + 64] = x2 * c - x1 * sn;
    }
    {
        float x1 = g_k[p + i], x2 = g_k[p + i + 64];
        g_k[p + i]      = x1 * c + x2 * sn;
        g_k[p + i + 64] = x2 * c - x1 * sn;
    }
}

// ---------------------------------------------------------------------------
// Causal flash attention, register-tiled (verified). Block = (64-row q-tile,
// one bh). 256 threads as 16x16.
// ---------------------------------------------------------------------------
__global__ __launch_bounds__(256, 1)
void attn_kernel()
{
    extern __shared__ float sm[];
    float* Qs = sm;                 // 64 x 128
    float* Ks = sm + 64*128;        // 64 x (stride 132)
    float* Vs = Ks + 64*132;        // 64 x 128
    float* Ps = Vs + 64*128;        // 64 x 64

    const int tid = threadIdx.x;
    const int qt = blockIdx.x;
    const int bh = blockIdx.y;      // b*16 + h
    const int ty = tid >> 4, tx = tid & 15;
    const float scale = 0.08838834764831845f;   // 1/sqrt(128)

    const size_t plane = (size_t)bh * 2048;

#pragma unroll
    for (int it = 0; it < 8; ++it) {
        int idx = tid + it * 256;
        int r = idx >> 5, c4 = (idx & 31) * 4;
        float4 v = *(const float4*)(g_q + (plane + qt*64 + r) * 128 + c4);
        v.x *= scale; v.y *= scale; v.z *= scale; v.w *= scale;
        *(float4*)&Qs[r*128 + c4] = v;
    }

    float m[4], l[4], o[4][8];
#pragma unroll
    for (int u = 0; u < 4; ++u) {
        m[u] = -INFINITY; l[u] = 0.f;
#pragma unroll
        for (int j = 0; j < 8; ++j) o[u][j] = 0.f;
    }

    for (int kt = 0; kt <= qt; ++kt) {
        __syncthreads();
#pragma unroll
        for (int it = 0; it < 8; ++it) {
            int idx = tid + it * 256;
            int r = idx >> 5, c4 = (idx & 31) * 4;
            *(float4*)&Ks[r*132 + c4] = *(const float4*)(g_k + (plane + kt*64 + r) * 128 + c4);
            *(float4*)&Vs[r*128 + c4] = *(const float4*)(g_v + (plane + kt*64 + r) * 128 + c4);
        }
        __syncthreads();

        float s4[4][4];
#pragma unroll
        for (int u = 0; u < 4; ++u)
#pragma unroll
            for (int v = 0; v < 4; ++v) s4[u][v] = 0.f;

#pragma unroll 4
        for (int d4 = 0; d4 < 32; ++d4) {
            float4 qv[4], kv[4];
#pragma unroll
            for (int u = 0; u < 4; ++u) qv[u] = *(const float4*)&Qs[(ty*4+u)*128 + d4*4];
#pragma unroll
            for (int v = 0; v < 4; ++v) kv[v] = *(const float4*)&Ks[(tx+16*v)*132 + d4*4];
#pragma unroll
            for (int u = 0; u < 4; ++u)
#pragma unroll
                for (int v = 0; v < 4; ++v) {
                    s4[u][v] = fmaf(qv[u].x, kv[v].x, s4[u][v]);
                    s4[u][v] = fmaf(qv[u].y, kv[v].y, s4[u][v]);
                    s4[u][v] = fmaf(qv[u].z, kv[v].z, s4[u][v]);
                    s4[u][v] = fmaf(qv[u].w, kv[v].w, s4[u][v]);
                }
        }

        if (kt == qt) {
#pragma unroll
            for (int u = 0; u < 4; ++u)
#pragma unroll
                for (int v = 0; v < 4; ++v)
                    if (tx + 16*v > ty*4 + u) s4[u][v] = -INFINITY;
        }

#pragma unroll
        for (int u = 0; u < 4; ++u) {
            float mx = fmaxf(fmaxf(s4[u][0], s4[u][1]), fmaxf(s4[u][2], s4[u][3]));
#pragma unroll
            for (int off = 1; off < 16; off <<= 1)
                mx = fmaxf(mx, __shfl_xor_sync(0xffffffffu, mx, off));
            float mn = fmaxf(m[u], mx);
            float f = expf(m[u] - mn);
            float pl = 0.f;
#pragma unroll
            for (int v = 0; v < 4; ++v) {
                float p = expf(s4[u][v] - mn);
                Ps[(ty*4+u)*64 + tx + 16*v] = p;
                pl += p;
            }
#pragma unroll
            for (int off = 1; off < 16; off <<= 1)
                pl += __shfl_xor_sync(0xffffffffu, pl, off);
            l[u] = l[u] * f + pl;
            m[u] = mn;
#pragma unroll
            for (int j = 0; j < 8; ++j) o[u][j] *= f;
        }
        __syncthreads();

#pragma unroll 4
        for (int kv2 = 0; kv2 < 64; ++kv2) {
            float4 v0 = *(const float4*)&Vs[kv2*128 + tx*4];
            float4 v1 = *(const float4*)&Vs[kv2*128 + 64 + tx*4];
#pragma unroll
            for (int u = 0; u < 4; ++u) {
                float p = Ps[(ty*4+u)*64 + kv2];
                o[u][0] = fmaf(p, v0.x, o[u][0]);
                o[u][1] = fmaf(p, v0.y, o[u][1]);
                o[u][2] = fmaf(p, v0.z, o[u][2]);
                o[u][3] = fmaf(p, v0.w, o[u][3]);
                o[u][4] = fmaf(p, v1.x, o[u][4]);
                o[u][5] = fmaf(p, v1.y, o[u][5]);
                o[u][6] = fmaf(p, v1.z, o[u][6]);
                o[u][7] = fmaf(p, v1.w, o[u][7]);
            }
        }
    }

    int b = bh >> 4, h = bh & 15;
#pragma unroll
    for (int u = 0; u < 4; ++u) {
        float inv = 1.f / l[u];
        size_t base = (size_t)(b*S_ + qt*64 + ty*4 + u) * D_ + h * DH_;
        *(float4*)(g_z + base + tx*4) =
            make_float4(o[u][0]*inv, o[u][1]*inv, o[u][2]*inv, o[u][3]*inv);
        *(float4*)(g_z + base + 64 + tx*4) =
            make_float4(o[u][4]*inv, o[u][5]*inv, o[u][6]*inv, o[u][7]*inv);
    }
}

// ---------------------------------------------------------------------------
extern "C" void kernel_launch(void* const* d_in, const int* in_sizes, int n_in,
                              void* d_out, int out_size)
{
    (void)out_size;
    const float* x    = nullptr;   // B*S*D   = 16,777,216
    const float* Wqkv = nullptr;   // 3*D*D   = 12,582,912
    const float* Wo   = nullptr;   // D*D     =  4,194,304
    for (int i = 0; i < n_in; ++i) {
        if      (in_sizes[i] == 16777216) x    = (const float*)d_in[i];
        else if (in_sizes[i] == 12582912) Wqkv = (const float*)d_in[i];
        else if (in_sizes[i] ==  4194304) Wo   = (const float*)d_in[i];
    }
    if (!x)    x    = (const float*)d_in[0];
    if (!Wqkv) Wqkv = (const float*)d_in[1];
    if (!Wo)   Wo   = (const float*)d_in[2];

    float* out = (float*)d_out;

    float *z = nullptr;
    __nv_bfloat16 *xh, *xl, *wh, *wl, *woh, *wol, *zh, *zl;
    cudaGetSymbolAddress((void**)&z,   g_z);
    cudaGetSymbolAddress((void**)&xh,  g_xh);  cudaGetSymbolAddress((void**)&xl,  g_xl);
    cudaGetSymbolAddress((void**)&wh,  g_wh);  cudaGetSymbolAddress((void**)&wl,  g_wl);
    cudaGetSymbolAddress((void**)&woh, g_woh); cudaGetSymbolAddress((void**)&wol, g_wol);
    cudaGetSymbolAddress((void**)&zh,  g_zh);  cudaGetSymbolAddress((void**)&zl,  g_zl);

    dim3 blk(256);
    const int gemm_smem = 2 * 4 * 128 * 40 * 2;   // 81,920 B
    cudaFuncSetAttribute(gemm3, cudaFuncAttributeMaxDynamicSharedMemorySize, gemm_smem);

    // 0) pre-split all GEMM operands to bf16 hi/lo
    split_kernel<<<(B_*S_*D_)/1024, blk>>>(x, xh, xl);
    split_kernel<<<(QKV_N*D_)/1024, blk>>>(Wqkv, wh, wl);
    split_kernel<<<(D_*D_)/1024,   blk>>>(Wo, woh, wol);

    // 1) planar q/k/v = x @ Wqkv^T  (pre-split bf16x3, cp.async pipelined)
    gemm3<<<dim3(QKV_N/128, (B_*S_)/128), blk, gemm_smem>>>(xh, xl, wh, wl, nullptr, QKV_N, D_, 1);

    // 2) RoPE in place on planar q,k (negated-angle half-split)
    rope_planar_kernel<<<(BH_*S_*64)/256, blk>>>();

    // 3) causal attention -> z  (register-tiled fp32)
    const int attn_smem = (64*128 + 64*132 + 64*128 + 64*64) * 4;   // 115,712 B
    cudaFuncSetAttribute(attn_kernel, cudaFuncAttributeMaxDynamicSharedMemorySize, attn_smem);
    attn_kernel<<<dim3(S_/64, BH_), blk, attn_smem>>>();

    // 4) split z, then out = z @ Wo^T
    split_kernel<<<(B_*S_*D_)/1024, blk>>>(z, zh, zl);
    gemm3<<<dim3(D_/128, (B_*S_)/128), blk, gemm_smem>>>(zh, zl, woh, wol, out, D_, D_, 0);
}

// round 17
// speedup vs baseline: 7.1257x; 1.3719x over previous
#include <cuda_runtime.h>
#include <cuda_bf16.h>
#include <cstdint>
#include <math.h>

#define B_ 4
#define S_ 2048
#define D_ 2048
#define H_ 16
#define DH_ 128
#define QKV_N (3*D_)
#define BH_ (B_*H_)

// fp32 planar scratch (gemm scatter targets)
__device__ float g_q[(size_t)BH_*S_*DH_];
__device__ float g_k[(size_t)BH_*S_*DH_];
__device__ float g_v[(size_t)BH_*S_*DH_];

// Pre-split bf16 operands
__device__ __nv_bfloat16 g_xh[(size_t)B_*S_*D_],  g_xl[(size_t)B_*S_*D_];
__device__ __nv_bfloat16 g_wh[(size_t)QKV_N*D_],  g_wl[(size_t)QKV_N*D_];
__device__ __nv_bfloat16 g_woh[(size_t)D_*D_],    g_wol[(size_t)D_*D_];
__device__ __nv_bfloat16 g_zh[(size_t)B_*S_*D_],  g_zl[(size_t)B_*S_*D_];
__device__ __nv_bfloat16 g_qh[(size_t)BH_*S_*DH_], g_ql[(size_t)BH_*S_*DH_];
__device__ __nv_bfloat16 g_kh[(size_t)BH_*S_*DH_], g_kl[(size_t)BH_*S_*DH_];
__device__ __nv_bfloat16 g_vth[(size_t)BH_*DH_*S_], g_vtl[(size_t)BH_*DH_*S_]; // [bh][dh][key]

__device__ __forceinline__ unsigned smem_u32(const void* p) {
    return (unsigned)__cvta_generic_to_shared(p);
}

#define LDSM4(r0,r1,r2,r3,addr) asm volatile( \
    "ldmatrix.sync.aligned.m8n8.x4.shared.b16 {%0,%1,%2,%3}, [%4];" \
    : "=r"(r0),"=r"(r1),"=r"(r2),"=r"(r3) : "r"(addr))

#define MMA16816(d,a,b0,b1) asm volatile( \
    "mma.sync.aligned.m16n8k16.row.col.f32.bf16.bf16.f32 " \
    "{%0,%1,%2,%3},{%4,%5,%6,%7},{%8,%9},{%0,%1,%2,%3};" \
    : "+f"((d)[0]),"+f"((d)[1]),"+f"((d)[2]),"+f"((d)[3]) \
    : "r"((a)[0]),"r"((a)[1]),"r"((a)[2]),"r"((a)[3]),"r"(b0),"r"(b1))

#define CP_ASYNC16(dst_u32, src_ptr) asm volatile( \
    "cp.async.ca.shared.global [%0], [%1], 16;" :: "r"(dst_u32), "l"(src_ptr))

__device__ __forceinline__ void split2(float v, __nv_bfloat16& h, __nv_bfloat16& l) {
    h = __float2bfloat16(v);
    l = __float2bfloat16(v - __bfloat162float(h));
}

// ---------------------------------------------------------------------------
__global__ void split_kernel(const float* __restrict__ src,
                             __nv_bfloat16* __restrict__ hi,
                             __nv_bfloat16* __restrict__ lo)
{
    size_t i = ((size_t)blockIdx.x * blockDim.x + threadIdx.x) * 4;
    float4 v = *(const float4*)(src + i);
    __nv_bfloat162 h01, h23, l01, l23;
    split2(v.x, h01.x, l01.x); split2(v.y, h01.y, l01.y);
    split2(v.z, h23.x, l23.x); split2(v.w, h23.y, l23.y);
    *(__nv_bfloat162*)(hi + i)     = h01;
    *(__nv_bfloat162*)(hi + i + 2) = h23;
    *(__nv_bfloat162*)(lo + i)     = l01;
    *(__nv_bfloat162*)(lo + i + 2) = l23;
}

// ---------------------------------------------------------------------------
// bf16x3 GEMM on pre-split inputs, cp.async double-buffered (verified R15).
// ---------------------------------------------------------------------------
__global__ __launch_bounds__(256)
void gemm3(const __nv_bfloat16* __restrict__ Ahg, const __nv_bfloat16* __restrict__ Alg,
           const __nv_bfloat16* __restrict__ Bhg, const __nv_bfloat16* __restrict__ Blg,
           float* __restrict__ C, int N, int K, int mode)
{
    extern __shared__ __nv_bfloat16 smem[];   // [2][4][128*40]

    const int tid  = threadIdx.x;
    const int bm   = blockIdx.y, bn = blockIdx.x;
    const int lane = tid & 31,  wid = tid >> 5;
    const int wm   = wid & 3,   wn  = wid >> 2;

    float acc[2][8][4];
#pragma unroll
    for (int mi = 0; mi < 2; ++mi)
#pragma unroll
        for (int n8 = 0; n8 < 8; ++n8)
#pragma unroll
            for (int t = 0; t < 4; ++t) acc[mi][n8][t] = 0.f;

    const __nv_bfloat16* gsrc[4] = {
        Ahg + (size_t)bm * 128 * K, Alg + (size_t)bm * 128 * K,
        Bhg + (size_t)bn * 128 * K, Blg + (size_t)bn * 128 * K };

    const int lrow = tid >> 2;
    const int lch  = (tid & 3) * 8;

    auto load_stage = [&](int st, int kt) {
#pragma unroll
        for (int arr = 0; arr < 4; ++arr) {
            const __nv_bfloat16* g = gsrc[arr];
            __nv_bfloat16* s = smem + (size_t)(st*4 + arr) * (128*40);
#pragma unroll
            for (int it = 0; it < 2; ++it) {
                int row = lrow + it * 64;
                CP_ASYNC16(smem_u32(s + row*40 + lch),
                           g + (size_t)row * K + kt + lch);
            }
        }
        asm volatile("cp.async.commit_group;" ::);
    };

    const int rsel = lane & 15;
    const int ksel = (lane >> 4) * 8;
    const int T = K / 32;

    load_stage(0, 0);

    for (int t = 0; t < T; ++t) {
        if (t + 1 < T) {
            load_stage((t + 1) & 1, (t + 1) * 32);
            asm volatile("cp.async.wait_group 1;" ::);
        } else {
            asm volatile("cp.async.wait_group 0;" ::);
        }
        __syncthreads();

        const int st = t & 1;
        const __nv_bfloat16* Ahs = smem + (size_t)(st*4 + 0) * (128*40);
        const __nv_bfloat16* Als = smem + (size_t)(st*4 + 1) * (128*40);
        const __nv_bfloat16* Bhs = smem + (size_t)(st*4 + 2) * (128*40);
        const __nv_bfloat16* Bls = smem + (size_t)(st*4 + 3) * (128*40);

#pragma unroll
        for (int kk = 0; kk < 32; kk += 16) {
            unsigned ah[2][4], al[2][4], bh[4][4], bl[4][4];
#pragma unroll
            for (int mi = 0; mi < 2; ++mi) {
                int off = (wm*32 + mi*16 + rsel)*40 + kk + ksel;
                LDSM4(ah[mi][0],ah[mi][1],ah[mi][2],ah[mi][3], smem_u32(Ahs + off));
                LDSM4(al[mi][0],al[mi][1],al[mi][2],al[mi][3], smem_u32(Als + off));
            }
#pragma unroll
            for (int nj = 0; nj < 4; ++nj) {
                int off = (wn*64 + nj*16 + rsel)*40 + kk + ksel;
                LDSM4(bh[nj][0],bh[nj][1],bh[nj][2],bh[nj][3], smem_u32(Bhs + off));
                LDSM4(bl[nj][0],bl[nj][1],bl[nj][2],bl[nj][3], smem_u32(Bls + off));
            }
#pragma unroll
            for (int mi = 0; mi < 2; ++mi)
#pragma unroll
                for (int nj = 0; nj < 4; ++nj)
#pragma unroll
                    for (int t2 = 0; t2 < 2; ++t2) {
                        float* d = acc[mi][nj*2 + t2];
                        MMA16816(d, ah[mi], bh[nj][t2], bh[nj][2+t2]);
                        MMA16816(d, ah[mi], bl[nj][t2], bl[nj][2+t2]);
                        MMA16816(d, al[mi], bh[nj][t2], bh[nj][2+t2]);
                    }
        }
        __syncthreads();
    }

    const int r_in = lane >> 2;
    const int c_in = (lane & 3) * 2;
    if (mode == 0) {
#pragma unroll
        for (int mi = 0; mi < 2; ++mi) {
            int m0 = bm*128 + wm*32 + mi*16 + r_in;
#pragma unroll
            for (int n8 = 0; n8 < 8; ++n8) {
                int col = bn*128 + wn*64 + n8*8 + c_in;
                *(float2*)&C[(size_t)m0*N + col] =
                    make_float2(acc[mi][n8][0], acc[mi][n8][1]);
                *(float2*)&C[(size_t)(m0+8)*N + col] =
                    make_float2(acc[mi][n8][2], acc[mi][n8][3]);
            }
        }
    } else {
        const int part = bn >> 4, hh = bn & 15;
        float* dst = (part == 0) ? g_q : (part == 1) ? g_k : g_v;
#pragma unroll
        for (int mi = 0; mi < 2; ++mi) {
            int m0 = bm*128 + wm*32 + mi*16 + r_in;
            int bb = m0 >> 11, ss = m0 & 2047;
            size_t r0 = ((size_t)(bb*16 + hh) * 2048 + ss) * 128;
            size_t r1 = r0 + 8 * 128;
#pragma unroll
            for (int n8 = 0; n8 < 8; ++n8) {
                int col = wn*64 + n8*8 + c_in;
                *(float2*)&dst[r0 + col] = make_float2(acc[mi][n8][0], acc[mi][n8][1]);
                *(float2*)&dst[r1 + col] = make_float2(acc[mi][n8][2], acc[mi][n8][3]);
            }
        }
    }
}

// ---------------------------------------------------------------------------
// RoPE (negated-angle half-split, verified) + bf16 hi/lo split.
// q additionally scaled by 1/sqrt(128).
// ---------------------------------------------------------------------------
__global__ void rope_split_kernel()
{
    const float scale = 0.08838834764831845f;
    int gid = blockIdx.x * blockDim.x + threadIdx.x;   // B*H*S*64 threads
    int i   = gid & 63;
    int row = gid >> 6;
    int s   = row & 2047;
    float inv = powf(10000.f, -(float)i / 64.f);
    float ang = (float)s * inv;
    float c, sn;
    sincosf(ang, &c, &sn);
    size_t p = (size_t)row * 128;
    {
        float x1 = g_q[p + i], x2 = g_q[p + i + 64];
        float r1 = (x1 * c + x2 * sn) * scale;
        float r2 = (x2 * c - x1 * sn) * scale;
        split2(r1, g_qh[p + i], g_ql[p + i]);
        split2(r2, g_qh[p + i + 64], g_ql[p + i + 64]);
    }
    {
        float x1 = g_k[p + i], x2 = g_k[p + i + 64];
        float r1 = x1 * c + x2 * sn;
        float r2 = x2 * c - x1 * sn;
        split2(r1, g_kh[p + i], g_kl[p + i]);
        split2(r2, g_kh[p + i + 64], g_kl[p + i + 64]);
    }
}

// ---------------------------------------------------------------------------
// V transpose + split: g_v [bh][key][dh] fp32 -> g_vth/g_vtl [bh][dh][key].
// 32x32 smem tiles. grid (dh/32, key/32, bh), block (32, 8).
// ---------------------------------------------------------------------------
__global__ void vsplitT_kernel()
{
    __shared__ float t[32][33];
    int bhp = blockIdx.z;
    int dh0 = blockIdx.x * 32, k0 = blockIdx.y * 32;
    int tx = threadIdx.x, ty = threadIdx.y;
    const float* src = g_v + (size_t)bhp * 2048 * 128;
#pragma unroll
    for (int j = 0; j < 4; ++j)
        t[ty + 8*j][tx] = src[(size_t)(k0 + ty + 8*j) * 128 + dh0 + tx];
    __syncthreads();
#pragma unroll
    for (int j = 0; j < 4; ++j) {
        int dh = dh0 + ty + 8*j, key = k0 + tx;
        float v = t[tx][ty + 8*j];
        size_t o = ((size_t)bhp * 128 + dh) * 2048 + key;
        split2(v, g_vth[o], g_vtl[o]);
    }
}

// ---------------------------------------------------------------------------
// Tensor-core causal flash attention (bf16x3 scores and PV).
// Block = 64-row q-tile x one bh, 256 threads, warp grid:
//   scores: 4(m) x 2(n) -> warp tile 16 x 32 over 64x64 S-tile
//   PV:     4(m) x 2(n) -> warp tile 16 x 64 over 64x128 O-tile
// smem strides: Q/K 136, Vt/P 72 (all conflict-free; all 16B-aligned rows).
// Writes zh/zl directly (split epilogue).
// ---------------------------------------------------------------------------
#define SQK 136
#define SVP 72
__global__ __launch_bounds__(256, 1)
void attn_tc_kernel()
{
    extern __shared__ __nv_bfloat16 sb[];
    __nv_bfloat16* Qh = sb;                    // 64*136
    __nv_bfloat16* Ql = Qh + 64*SQK;
    __nv_bfloat16* Kh = Ql + 64*SQK;
    __nv_bfloat16* Kl = Kh + 64*SQK;
    __nv_bfloat16* Vh = Kl + 64*SQK;           // 128*72 (transposed: [dh][key])
    __nv_bfloat16* Vl = Vh + 128*SVP;
    __nv_bfloat16* Ph = Vl + 128*SVP;          // 64*72
    __nv_bfloat16* Pl = Ph + 64*SVP;
    float* stats = (float*)(Pl + 64*SVP);
    float* sm_m = stats;            // [64]
    float* sm_l = sm_m + 64;        // [64]
    float* sm_f = sm_l + 64;        // [64]
    float* sm_cm = sm_f + 64;       // [2][64]
    float* sm_cs = sm_cm + 128;     // [2][64]

    const int tid  = threadIdx.x;
    const int qt   = gridDim.x - 1 - blockIdx.x;
    const int bh   = blockIdx.y;
    const int lane = tid & 31, wid = tid >> 5;
    const int wm   = wid & 3,  wn  = wid >> 2;
    const int rsel = lane & 15;
    const int ksel = (lane >> 4) * 8;
    const int r_in = lane >> 2;
    const int c_in = (lane & 3) * 2;

    const size_t plane = (size_t)bh * 2048;

    // Q tile cp.async (64 rows x 128 bf16, both hi/lo)
    {
        const __nv_bfloat16* qh = g_qh + (plane + qt*64) * 128;
        const __nv_bfloat16* ql = g_ql + (plane + qt*64) * 128;
#pragma unroll
        for (int it = 0; it < 4; ++it) {
            int idx = tid + it * 256;           // 1024 chunks
            int row = idx >> 4, ch = (idx & 15) * 8;
            CP_ASYNC16(smem_u32(Qh + row*SQK + ch), qh + (size_t)row*128 + ch);
            CP_ASYNC16(smem_u32(Ql + row*SQK + ch), ql + (size_t)row*128 + ch);
        }
        asm volatile("cp.async.commit_group;" ::);
    }

    if (tid < 64) { sm_m[tid] = -INFINITY; sm_l[tid] = 0.f; }

    float o[8][4];
#pragma unroll
    for (int n8 = 0; n8 < 8; ++n8)
#pragma unroll
        for (int t = 0; t < 4; ++t) o[n8][t] = 0.f;

    for (int kt = 0; kt <= qt; ++kt) {
        __syncthreads();   // P/K/V readers of prev iter done; stats init visible
        {
            const __nv_bfloat16* kh = g_kh + (plane + kt*64) * 128;
            const __nv_bfloat16* kl = g_kl + (plane + kt*64) * 128;
            const __nv_bfloat16* vh = g_vth + ((size_t)bh*128) * 2048 + kt*64;
            const __nv_bfloat16* vl = g_vtl + ((size_t)bh*128) * 2048 + kt*64;
#pragma unroll
            for (int it = 0; it < 4; ++it) {
                int idx = tid + it * 256;
                int row = idx >> 4, ch = (idx & 15) * 8;
                CP_ASYNC16(smem_u32(Kh + row*SQK + ch), kh + (size_t)row*128 + ch);
                CP_ASYNC16(smem_u32(Kl + row*SQK + ch), kl + (size_t)row*128 + ch);
            }
#pragma unroll
            for (int it = 0; it < 4; ++it) {
                int idx = tid + it * 256;       // 1024 chunks: 128 rows x 8
                int row = idx >> 3, ch = (idx & 7) * 8;
                CP_ASYNC16(smem_u32(Vh + row*SVP + ch), vh + (size_t)row*2048 + ch);
                CP_ASYNC16(smem_u32(Vl + row*SVP + ch), vl + (size_t)row*2048 + ch);
            }
            asm volatile("cp.async.commit_group;" ::);
            asm volatile("cp.async.wait_group 0;" ::);
        }
        __syncthreads();

        // ---- scores S = Q K^T (bf16x3) ----
        float s[4][4];
#pragma unroll
        for (int n8 = 0; n8 < 4; ++n8)
#pragma unroll
            for (int t = 0; t < 4; ++t) s[n8][t] = 0.f;

#pragma unroll
        for (int kk = 0; kk < 128; kk += 16) {
            unsigned ah[4], al[4], bh[2][4], bl[2][4];
            int aoff = (wm*16 + rsel)*SQK + kk + ksel;
            LDSM4(ah[0],ah[1],ah[2],ah[3], smem_u32(Qh + aoff));
            LDSM4(al[0],al[1],al[2],al[3], smem_u32(Ql + aoff));
#pragma unroll
            for (int nj = 0; nj < 2; ++nj) {
                int boff = (wn*32 + nj*16 + rsel)*SQK + kk + ksel;
                LDSM4(bh[nj][0],bh[nj][1],bh[nj][2],bh[nj][3], smem_u32(Kh + boff));
                LDSM4(bl[nj][0],bl[nj][1],bl[nj][2],bl[nj][3], smem_u32(Kl + boff));
            }
#pragma unroll
            for (int nj = 0; nj < 2; ++nj)
#pragma unroll
                for (int t = 0; t < 2; ++t) {
                    float* d = s[nj*2 + t];
                    MMA16816(d, ah, bh[nj][t], bh[nj][2+t]);
                    MMA16816(d, ah, bl[nj][t], bl[nj][2+t]);
                    MMA16816(d, al, bh[nj][t], bh[nj][2+t]);
                }
        }

        // ---- causal mask on diagonal tile ----
        if (kt == qt) {
            int row0 = wm*16 + r_in;
#pragma unroll
            for (int n8 = 0; n8 < 4; ++n8)
#pragma unroll
                for (int t = 0; t < 2; ++t) {
                    int col = wn*32 + n8*8 + c_in + t;
                    if (col > row0)     s[n8][t]   = -INFINITY;
                    if (col > row0 + 8) s[n8][2+t] = -INFINITY;
                }
        }

        // ---- row max (in-warp quad + cross-warp via smem) ----
        float m0 = -INFINITY, m1 = -INFINITY;
#pragma unroll
        for (int n8 = 0; n8 < 4; ++n8) {
            m0 = fmaxf(m0, fmaxf(s[n8][0], s[n8][1]));
            m1 = fmaxf(m1, fmaxf(s[n8][2], s[n8][3]));
        }
#pragma unroll
        for (int off = 1; off < 4; off <<= 1) {
            m0 = fmaxf(m0, __shfl_xor_sync(0xffffffffu, m0, off));
            m1 = fmaxf(m1, __shfl_xor_sync(0xffffffffu, m1, off));
        }
        if ((lane & 3) == 0) {
            sm_cm[wn*64 + wm*16 + r_in]     = m0;
            sm_cm[wn*64 + wm*16 + r_in + 8] = m1;
        }
        __syncthreads();
        if (tid < 64) {
            float mn = fmaxf(sm_m[tid], fmaxf(sm_cm[tid], sm_cm[64 + tid]));
            sm_f[tid] = __expf(sm_m[tid] - mn);
            sm_m[tid] = mn;
        }
        __syncthreads();

        // ---- P = exp(S - m), write bf16 hi/lo, partial row sums ----
        {
            int row0 = wm*16 + r_in;
            float mn0 = sm_m[row0], mn1 = sm_m[row0 + 8];
            float s0 = 0.f, s1 = 0.f;
#pragma unroll
            for (int n8 = 0; n8 < 4; ++n8) {
                int col = wn*32 + n8*8 + c_in;
                float p00 = __expf(s[n8][0] - mn0);
                float p01 = __expf(s[n8][1] - mn0);
                float p10 = __expf(s[n8][2] - mn1);
                float p11 = __expf(s[n8][3] - mn1);
                s0 += p00 + p01; s1 += p10 + p11;
                __nv_bfloat162 h0, l0, h1, l1;
                split2(p00, h0.x, l0.x); split2(p01, h0.y, l0.y);
                split2(p10, h1.x, l1.x); split2(p11, h1.y, l1.y);
                *(__nv_bfloat162*)&Ph[row0*SVP + col]       = h0;
                *(__nv_bfloat162*)&Pl[row0*SVP + col]       = l0;
                *(__nv_bfloat162*)&Ph[(row0+8)*SVP + col]   = h1;
                *(__nv_bfloat162*)&Pl[(row0+8)*SVP + col]   = l1;
            }
#pragma unroll
            for (int off = 1; off < 4; off <<= 1) {
                s0 += __shfl_xor_sync(0xffffffffu, s0, off);
                s1 += __shfl_xor_sync(0xffffffffu, s1, off);
            }
            if ((lane & 3) == 0) {
                sm_cs[wn*64 + row0]     = s0;
                sm_cs[wn*64 + row0 + 8] = s1;
            }
            // rescale o by f
            float f0 = sm_f[row0], f1 = sm_f[row0 + 8];
#pragma unroll
            for (int n8 = 0; n8 < 8; ++n8) {
                o[n8][0] *= f0; o[n8][1] *= f0;
                o[n8][2] *= f1; o[n8][3] *= f1;
            }
        }
        __syncthreads();
        if (tid < 64)
            sm_l[tid] = sm_l[tid] * sm_f[tid] + sm_cs[tid] + sm_cs[64 + tid];

        // ---- O += P V (bf16x3) ----
#pragma unroll
        for (int kk = 0; kk < 64; kk += 16) {
            unsigned ah[4], al[4], bh[4][4], bl[4][4];
            int aoff = (wm*16 + rsel)*SVP + kk + ksel;
            LDSM4(ah[0],ah[1],ah[2],ah[3], smem_u32(Ph + aoff));
            LDSM4(al[0],al[1],al[2],al[3], smem_u32(Pl + aoff));
#pragma unroll
            for (int nj = 0; nj < 4; ++nj) {
                int boff = (wn*64 + nj*16 + rsel)*SVP + kk + ksel;
                LDSM4(bh[nj][0],bh[nj][1],bh[nj][2],bh[nj][3], smem_u32(Vh + boff));
                LDSM4(bl[nj][0],bl[nj][1],bl[nj][2],bl[nj][3], smem_u32(Vl + boff));
            }
#pragma unroll
            for (int nj = 0; nj < 4; ++nj)
#pragma unroll
                for (int t = 0; t < 2; ++t) {
                    float* d = o[nj*2 + t];
                    MMA16816(d, ah, bh[nj][t], bh[nj][2+t]);
                    MMA16816(d, ah, bl[nj][t], bl[nj][2+t]);
                    MMA16816(d, al, bh[nj][t], bh[nj][2+t]);
                }
        }
    }
    __syncthreads();   // sm_l final values visible

    // ---- epilogue: z = O / l, split to zh/zl ----
    {
        int row0 = wm*16 + r_in;
        float il0 = 1.f / sm_l[row0], il1 = 1.f / sm_l[row0 + 8];
        int b = bh >> 4, h = bh & 15;
        size_t base0 = (size_t)(b*S_ + qt*64 + row0) * D_ + h * DH_;
        size_t base1 = base0 + 8 * D_;
#pragma unroll
        for (int n8 = 0; n8 < 8; ++n8) {
            int col = wn*64 + n8*8 + c_in;
            __nv_bfloat162 h2, l2;
            split2(o[n8][0]*il0, h2.x, l2.x); split2(o[n8][1]*il0, h2.y, l2.y);
            *(__nv_bfloat162*)&g_zh[base0 + col] = h2;
            *(__nv_bfloat162*)&g_zl[base0 + col] = l2;
            split2(o[n8][2]*il1, h2.x, l2.x); split2(o[n8][3]*il1, h2.y, l2.y);
            *(__nv_bfloat162*)&g_zh[base1 + col] = h2;
            *(__nv_bfloat162*)&g_zl[base1 + col] = l2;
        }
    }
}

// ---------------------------------------------------------------------------
extern "C" void kernel_launch(void* const* d_in, const int* in_sizes, int n_in,
                              void* d_out, int out_size)
{
    (void)out_size;
    const float* x    = nullptr;
    const float* Wqkv = nullptr;
    const float* Wo   = nullptr;
    for (int i = 0; i < n_in; ++i) {
        if      (in_sizes[i] == 16777216) x    = (const float*)d_in[i];
        else if (in_sizes[i] == 12582912) Wqkv = (const float*)d_in[i];
        else if (in_sizes[i] ==  4194304) Wo   = (const float*)d_in[i];
    }
    if (!x)    x    = (const float*)d_in[0];
    if (!Wqkv) Wqkv = (const float*)d_in[1];
    if (!Wo)   Wo   = (const float*)d_in[2];

    float* out = (float*)d_out;

    __nv_bfloat16 *xh, *xl, *wh, *wl, *woh, *wol, *zh, *zl;
    cudaGetSymbolAddress((void**)&xh,  g_xh);  cudaGetSymbolAddress((void**)&xl,  g_xl);
    cudaGetSymbolAddress((void**)&wh,  g_wh);  cudaGetSymbolAddress((void**)&wl,  g_wl);
    cudaGetSymbolAddress((void**)&woh, g_woh); cudaGetSymbolAddress((void**)&wol, g_wol);
    cudaGetSymbolAddress((void**)&zh,  g_zh);  cudaGetSymbolAddress((void**)&zl,  g_zl);

    dim3 blk(256);
    const int gemm_smem = 2 * 4 * 128 * 40 * 2;   // 81,920 B
    cudaFuncSetAttribute(gemm3, cudaFuncAttributeMaxDynamicSharedMemorySize, gemm_smem);

    // 0) pre-split GEMM operands
    split_kernel<<<(B_*S_*D_)/1024, blk>>>(x, xh, xl);
    split_kernel<<<(QKV_N*D_)/1024, blk>>>(Wqkv, wh, wl);
    split_kernel<<<(D_*D_)/1024,   blk>>>(Wo, woh, wol);

    // 1) planar q/k/v = x @ Wqkv^T
    gemm3<<<dim3(QKV_N/128, (B_*S_)/128), blk, gemm_smem>>>(xh, xl, wh, wl, nullptr, QKV_N, D_, 1);

    // 2) RoPE + split q/k; transpose+split v
    rope_split_kernel<<<(BH_*S_*64)/256, blk>>>();
    vsplitT_kernel<<<dim3(DH_/32, S_/32, BH_), dim3(32, 8)>>>();

    // 3) tensor-core causal attention -> zh/zl
    const int attn_smem = (4*64*SQK + 2*128*SVP + 2*64*SVP) * 2 + 448 * 4;
    cudaFuncSetAttribute(attn_tc_kernel, cudaFuncAttributeMaxDynamicSharedMemorySize, attn_smem);
    attn_tc_kernel<<<dim3(S_/64, BH_), blk, attn_smem>>>();

    // 4) out = z @ Wo^T
    gemm3<<<dim3(D_/128, (B_*S_)/128), blk, gemm_smem>>>(zh, zl, woh, wol, out, D_, D_, 0);
}